// round 16
// baseline (speedup 1.0000x reference)
#include <cuda_runtime.h>
#include <cuda_fp16.h>
#include <cstdint>

#define T_TOKENS 2048
#define DMODEL   1024
#define DFF      4096
#define NEXP     8
#define MAXPER   2048

#define BM 128
#define BN 128
#define BK 32
#define AKH 40                       // A smem row stride (halves)
#define NST 136                      // B smem k-row stride (halves)
#define ABUF_H (BM * AKH)            // 5120 halves
#define BBUF_H (BK * NST)            // 4352 halves
#define SMEM_BYTES ((3 * ABUF_H + 2 * BBUF_H) * 2)   // ~47 KB -> 2 CTAs/SM

// ---- device scratch (static, no runtime allocation) ----
__device__ int    g_cnt[NEXP];
__device__ int    g_tok[NEXP * MAXPER];
__device__ float  g_wt [NEXP * MAXPER];
__device__ __half g_xh [(size_t)T_TOKENS * DMODEL];
__device__ __half g_h  [(size_t)NEXP * MAXPER * DFF];

// ---------------------------------------------------------------------------
__device__ __forceinline__ uint32_t smem_u32(const void* p) {
    uint32_t a;
    asm("{ .reg .u64 t; cvta.to.shared.u64 t, %1; cvt.u32.u64 %0, t; }"
        : "=r"(a) : "l"(p));
    return a;
}
#define CP_ASYNC16(dst, src) \
    asm volatile("cp.async.cg.shared.global [%0], [%1], 16;" \
                 :: "r"(dst), "l"(src))
#define CP_COMMIT()  asm volatile("cp.async.commit_group;")
#define CP_WAIT1()   asm volatile("cp.async.wait_group 1;")
#define CP_WAIT0()   asm volatile("cp.async.wait_group 0;")
#define LDSM4(r0, r1, r2, r3, addr)                                          \
    asm volatile("ldmatrix.sync.aligned.m8n8.x4.shared.b16 "                 \
                 "{%0,%1,%2,%3}, [%4];"                                      \
                 : "=r"(r0), "=r"(r1), "=r"(r2), "=r"(r3) : "r"(addr))
#define LDSM4T(r0, r1, r2, r3, addr)                                         \
    asm volatile("ldmatrix.sync.aligned.m8n8.x4.trans.shared.b16 "           \
                 "{%0,%1,%2,%3}, [%4];"                                      \
                 : "=r"(r0), "=r"(r1), "=r"(r2), "=r"(r3) : "r"(addr))
#define REDG_V2(addr, v0, v1)                                                \
    asm volatile("red.global.add.v2.f32 [%0], {%1, %2};"                     \
                 :: "l"(addr), "f"(v0), "f"(v1) : "memory")

// ---------------------------------------------------------------------------
// tiny reset: 8 expert counters
__global__ void reset_kernel(void) {
    if (threadIdx.x < NEXP) g_cnt[threadIdx.x] = 0;
}

// fused routing kernel: one block per token.
//  - converts this token's x row to fp16 (g_xh)
//  - zeroes this token's out row
//  - computes gate logits (one warp per expert), top-2 + softmax, appends
__global__ void route_kernel(const float* __restrict__ x,
                             const float* __restrict__ wg,
                             const float* __restrict__ bg,
                             float* __restrict__ out) {
    int t = blockIdx.x, warp = threadIdx.x >> 5, lane = threadIdx.x & 31;
    __shared__ float logits[NEXP];
    const float* xr = x + (size_t)t * DMODEL;

    // fused: convert x row to fp16 + zero out row (4 elems / thread)
    {
        const int i4 = threadIdx.x * 4;
        float4 v = *(const float4*)(xr + i4);
        __half2 lo = __floats2half2_rn(v.x, v.y);
        __half2 hi = __floats2half2_rn(v.z, v.w);
        *(uint2*)(g_xh + (size_t)t * DMODEL + i4) =
            make_uint2(*(uint32_t*)&lo, *(uint32_t*)&hi);
        *(float4*)(out + (size_t)t * DMODEL + i4) =
            make_float4(0.f, 0.f, 0.f, 0.f);
    }

    float s = 0.0f;
    #pragma unroll 8
    for (int d = lane; d < DMODEL; d += 32)
        s += xr[d] * __ldg(&wg[d * NEXP + warp]);
    #pragma unroll
    for (int o = 16; o; o >>= 1) s += __shfl_down_sync(0xffffffffu, s, o);
    if (lane == 0) logits[warp] = s + bg[warp];
    __syncthreads();
    if (threadIdx.x == 0) {
        int i0 = 0; float v0 = logits[0];
        #pragma unroll
        for (int e = 1; e < NEXP; e++)
            if (logits[e] > v0) { v0 = logits[e]; i0 = e; }
        int i1 = -1; float v1 = -3.0e38f;
        #pragma unroll
        for (int e = 0; e < NEXP; e++)
            if (e != i0 && logits[e] > v1) { v1 = logits[e]; i1 = e; }
        float e1 = __expf(v1 - v0);
        float inv = 1.0f / (1.0f + e1);
        int p0 = atomicAdd(&g_cnt[i0], 1);
        g_tok[i0 * MAXPER + p0] = t; g_wt[i0 * MAXPER + p0] = inv;
        int p1 = atomicAdd(&g_cnt[i1], 1);
        g_tok[i1 * MAXPER + p1] = t; g_wt[i1 * MAXPER + p1] = e1 * inv;
    }
}

// ===========================================================================
// Grouped GEMM, mma.sync m16n8k16 fp16 — R8 configuration (best known):
// CTA 128x128, 8 warps of 64x32, BK=32; A fp16 gmem -> 3-slot cp.async;
// B f32 gmem -> LDG.128 (+cvt) -> STS.64, double-buffered; two syncs/chunk.
// 2 CTAs/SM (16 warps). gemm2 epilogue uses vectorized red.global.add.v2.f32.
// ===========================================================================
template <bool G1>
__global__ __launch_bounds__(256, 2)
void moe_gemm(const float* __restrict__ w,
              const float* __restrict__ bias,
              float* __restrict__ out) {
    constexpr int K  = G1 ? DMODEL : DFF;
    constexpr int NG = G1 ? DFF : DMODEL;
    constexpr int NC = K / BK;

    const int e = blockIdx.z;
    const int n = g_cnt[e];
    const int row0 = blockIdx.y * BM;
    if (row0 >= n) return;
    const int col0 = blockIdx.x * BN;

    extern __shared__ __half sm[];
    __half* As = sm;                    // [3][BM][AKH]
    __half* Bs = sm + 3 * ABUF_H;       // [2][BK][NST]

    const int tid = threadIdx.x, lane = tid & 31, wid = tid >> 5;
    const int wm = (wid & 1) * 64, wn = (wid >> 1) * 32;

    // ---- A fill: 2 threads/row, 16 halves (32B) each per chunk ----
    const int ar = tid >> 1, ac = (tid & 1) * 16;
    const int rr = min(row0 + ar, n - 1);
    const __half* Ag;
    if (G1) Ag = g_xh + (size_t)g_tok[e * MAXPER + rr] * DMODEL + ac;
    else    Ag = g_h + ((size_t)e * MAXPER + rr) * DFF + ac;
    const uint32_t AsW = smem_u32(As) + (uint32_t)(ar * AKH + ac) * 2;

    // ---- B fill: 4 k-rows x 4 consecutive n per thread (LDG.128) ----
    const int bq  = (tid & 31) * 4;
    const int bk4 = (tid >> 5) * 4;
    const float* Bg = w + (size_t)e * DMODEL * DFF
                        + (size_t)bk4 * NG + col0 + bq;
    const uint32_t BsW = smem_u32(Bs) + (uint32_t)(bk4 * NST + bq) * 2;

    // ---- ldmatrix lane addresses (bytes) ----
    const uint32_t aFrag = smem_u32(As)
        + (uint32_t)(((wm + (lane & 15)) * AKH + (lane >> 4) * 8) * 2);
    const uint32_t bFrag = smem_u32(Bs)
        + (uint32_t)((((lane & 7) + ((lane >> 3) & 1) * 8) * NST
                      + wn + (lane >> 4) * 8) * 2);

    uint2 bqv[4];   // prefetched B chunk (converted fp16x2 at load)

    #define LDG_B(c)                                                         \
        do { _Pragma("unroll")                                               \
             for (int i = 0; i < 4; i++) {                                   \
                 float4 v = *(const float4*)                                 \
                     (Bg + (size_t)((c) * BK + i) * NG);                     \
                 __half2 lo = __floats2half2_rn(v.x, v.y);                   \
                 __half2 hi = __floats2half2_rn(v.z, v.w);                   \
                 bqv[i] = make_uint2(*(uint32_t*)&lo, *(uint32_t*)&hi);      \
             }                                                               \
        } while (0)

    #define STS_B(buf)                                                       \
        do { _Pragma("unroll")                                               \
             for (int i = 0; i < 4; i++)                                     \
                 asm volatile("st.shared.v2.b32 [%0], {%1, %2};" ::          \
                     "r"(BsW + (buf) * (BBUF_H * 2) + i * (NST * 2)),        \
                     "r"(bqv[i].x), "r"(bqv[i].y));                          \
        } while (0)

    #define CPA_A(c, slot)                                                   \
        do {                                                                  \
            const __half* ag = Ag + (c) * BK;                                 \
            const uint32_t aw = AsW + (slot) * (ABUF_H * 2);                  \
            CP_ASYNC16(aw, ag);                                               \
            CP_ASYNC16(aw + 16, ag + 8);                                      \
            CP_COMMIT();                                                      \
        } while (0)

    float acc[4][4][4];
    #pragma unroll
    for (int a = 0; a < 4; a++)
        #pragma unroll
        for (int b = 0; b < 4; b++)
            #pragma unroll
            for (int c = 0; c < 4; c++) acc[a][b][c] = 0.0f;

    // ---- prologue ----
    LDG_B(0);
    STS_B(0);
    CPA_A(0, 0);
    if (NC > 1) { CPA_A(1, 1); LDG_B(1); CP_WAIT1(); }
    else        { CP_WAIT0(); }
    __syncthreads();

    // ---- main loop: A rotates over 3 slots, B over 2 buffers ----
    int cur = 0;
    for (int c = 0; c < NC; c++) {
        const uint32_t aB = aFrag + cur * (ABUF_H * 2);
        const uint32_t bB = bFrag + (c & 1) * (BBUF_H * 2);

        #pragma unroll
        for (int ks = 0; ks < 2; ks++) {
            uint32_t af[4][4];
            #pragma unroll
            for (int mt = 0; mt < 4; mt++)
                LDSM4(af[mt][0], af[mt][1], af[mt][2], af[mt][3],
                      aB + mt * (16 * AKH * 2) + ks * 32);
            uint32_t bf[4][2];
            LDSM4T(bf[0][0], bf[0][1], bf[1][0], bf[1][1],
                   bB + ks * (16 * NST * 2));
            LDSM4T(bf[2][0], bf[2][1], bf[3][0], bf[3][1],
                   bB + ks * (16 * NST * 2) + 32);
            #pragma unroll
            for (int mt = 0; mt < 4; mt++)
                #pragma unroll
                for (int nt = 0; nt < 4; nt++)
                    asm volatile(
                        "mma.sync.aligned.m16n8k16.row.col.f32.f16.f16.f32 "
                        "{%0,%1,%2,%3},{%4,%5,%6,%7},{%8,%9},{%0,%1,%2,%3};"
                        : "+f"(acc[mt][nt][0]), "+f"(acc[mt][nt][1]),
                          "+f"(acc[mt][nt][2]), "+f"(acc[mt][nt][3])
                        : "r"(af[mt][0]), "r"(af[mt][1]),
                          "r"(af[mt][2]), "r"(af[mt][3]),
                          "r"(bf[nt][0]), "r"(bf[nt][1]));
        }
        __syncthreads();                 // everyone done reading buf c&1

        if (c + 1 < NC) {
            STS_B((c + 1) & 1);          // bqv holds chunk c+1
            if (c + 2 < NC) {
                int slot2 = cur >= 1 ? cur - 1 : cur + 2;   // (c+2)%3
                CPA_A(c + 2, slot2);
                LDG_B(c + 2);
                CP_WAIT1();              // A(c+1) arrived
            } else {
                CP_WAIT0();
            }
            __syncthreads();             // B(c+1) visible
        }
        cur = (cur < 2) ? cur + 1 : 0;
    }

    // ---- epilogue ----
    #pragma unroll
    for (int mt = 0; mt < 4; mt++) {
        #pragma unroll
        for (int half = 0; half < 2; half++) {
            const int r = row0 + wm + mt * 16 + (lane >> 2) + half * 8;
            if (r >= n) continue;
            if (G1) {
                __half* Hp = g_h + ((size_t)e * MAXPER + r) * DFF + col0 + wn;
                const float* bp = bias + (size_t)e * DFF + col0 + wn;
                #pragma unroll
                for (int nt = 0; nt < 4; nt++) {
                    const int cc = nt * 8 + 2 * (lane & 3);
                    float2 b2v = *(const float2*)(bp + cc);
                    float vx = fmaxf(acc[mt][nt][half * 2 + 0] + b2v.x, 0.0f);
                    float vy = fmaxf(acc[mt][nt][half * 2 + 1] + b2v.y, 0.0f);
                    *(__half2*)(Hp + cc) = __floats2half2_rn(vx, vy);
                }
            } else {
                const int   tok = g_tok[e * MAXPER + r];
                const float wt  = g_wt [e * MAXPER + r];
                float* op = out + (size_t)tok * DMODEL + col0 + wn;
                const float* bp = bias + (size_t)e * DMODEL + col0 + wn;
                #pragma unroll
                for (int nt = 0; nt < 4; nt++) {
                    const int cc = nt * 8 + 2 * (lane & 3);
                    float2 b2v = *(const float2*)(bp + cc);
                    float v0 = wt * (acc[mt][nt][half * 2 + 0] + b2v.x);
                    float v1 = wt * (acc[mt][nt][half * 2 + 1] + b2v.y);
                    REDG_V2(op + cc, v0, v1);
                }
            }
        }
    }
    #undef LDG_B
    #undef STS_B
    #undef CPA_A
}

// ===========================================================================
extern "C" void kernel_launch(void* const* d_in, const int* in_sizes, int n_in,
                              void* d_out, int out_size) {
    const float* x  = (const float*)d_in[0];
    const float* wg = (const float*)d_in[1];
    const float* bg = (const float*)d_in[2];
    const float* w1 = (const float*)d_in[3];
    const float* b1 = (const float*)d_in[4];
    const float* w2 = (const float*)d_in[5];
    const float* b2 = (const float*)d_in[6];
    float* out = (float*)d_out;

    cudaFuncSetAttribute(moe_gemm<true>,
                         cudaFuncAttributeMaxDynamicSharedMemorySize, SMEM_BYTES);
    cudaFuncSetAttribute(moe_gemm<false>,
                         cudaFuncAttributeMaxDynamicSharedMemorySize, SMEM_BYTES);

    reset_kernel<<<1, 32>>>();
    route_kernel<<<T_TOKENS, 256>>>(x, wg, bg, out);
    moe_gemm<true ><<<dim3(DFF / BN,    MAXPER / BM, NEXP), 256, SMEM_BYTES>>>
        (w1, b1, nullptr);
    moe_gemm<false><<<dim3(DMODEL / BN, MAXPER / BM, NEXP), 256, SMEM_BYTES>>>
        (w2, b2, out);
}

// round 17
// speedup vs baseline: 1.1098x; 1.1098x over previous
#include <cuda_runtime.h>
#include <cuda_fp16.h>
#include <cstdint>

#define T_TOKENS 2048
#define DMODEL   1024
#define DFF      4096
#define NEXP     8
#define MAXPER   2048

#define BM 128
#define BN 128
#define BK 32
#define AKH 40                       // A smem row stride (halves)
#define NST 136                      // B smem k-row stride (halves)
#define ABUF_H (BM * AKH)            // 5120 halves
#define BBUF_H (BK * NST)            // 4352 halves
#define SMEM_BYTES ((3 * ABUF_H + 2 * BBUF_H) * 2)   // ~47 KB -> 2 CTAs/SM

// ---- device scratch (static, no runtime allocation) ----
__device__ int    g_cnt[NEXP];
__device__ int    g_tok[NEXP * MAXPER];
__device__ float  g_wt [NEXP * MAXPER];
__device__ __half g_xh [(size_t)T_TOKENS * DMODEL];
__device__ __half g_h  [(size_t)NEXP * MAXPER * DFF];

// ---------------------------------------------------------------------------
__device__ __forceinline__ uint32_t smem_u32(const void* p) {
    uint32_t a;
    asm("{ .reg .u64 t; cvta.to.shared.u64 t, %1; cvt.u32.u64 %0, t; }"
        : "=r"(a) : "l"(p));
    return a;
}
#define CP_ASYNC16(dst, src) \
    asm volatile("cp.async.cg.shared.global [%0], [%1], 16;" \
                 :: "r"(dst), "l"(src))
#define CP_COMMIT()  asm volatile("cp.async.commit_group;")
#define CP_WAIT1()   asm volatile("cp.async.wait_group 1;")
#define CP_WAIT0()   asm volatile("cp.async.wait_group 0;")
#define LDSM4(r0, r1, r2, r3, addr)                                          \
    asm volatile("ldmatrix.sync.aligned.m8n8.x4.shared.b16 "                 \
                 "{%0,%1,%2,%3}, [%4];"                                      \
                 : "=r"(r0), "=r"(r1), "=r"(r2), "=r"(r3) : "r"(addr))
#define LDSM4T(r0, r1, r2, r3, addr)                                         \
    asm volatile("ldmatrix.sync.aligned.m8n8.x4.trans.shared.b16 "           \
                 "{%0,%1,%2,%3}, [%4];"                                      \
                 : "=r"(r0), "=r"(r1), "=r"(r2), "=r"(r3) : "r"(addr))

// ---------------------------------------------------------------------------
__global__ void init_kernel(const float* __restrict__ x,
                            float* __restrict__ out, int out_size) {
    int i = blockIdx.x * blockDim.x + threadIdx.x;
    int stride = gridDim.x * blockDim.x;
    if (blockIdx.x == 0 && threadIdx.x < NEXP) g_cnt[threadIdx.x] = 0;
    for (int j = i; j < out_size; j += stride) out[j] = 0.0f;
    for (int j = i; j < T_TOKENS * DMODEL; j += stride)
        g_xh[j] = __float2half_rn(x[j]);
}

__global__ void route_kernel(const float* __restrict__ x,
                             const float* __restrict__ wg,
                             const float* __restrict__ bg) {
    int t = blockIdx.x, warp = threadIdx.x >> 5, lane = threadIdx.x & 31;
    __shared__ float logits[NEXP];
    const float* xr = x + (size_t)t * DMODEL;
    float s = 0.0f;
    #pragma unroll 8
    for (int d = lane; d < DMODEL; d += 32)
        s += xr[d] * __ldg(&wg[d * NEXP + warp]);
    #pragma unroll
    for (int o = 16; o; o >>= 1) s += __shfl_down_sync(0xffffffffu, s, o);
    if (lane == 0) logits[warp] = s + bg[warp];
    __syncthreads();
    if (threadIdx.x == 0) {
        int i0 = 0; float v0 = logits[0];
        #pragma unroll
        for (int e = 1; e < NEXP; e++)
            if (logits[e] > v0) { v0 = logits[e]; i0 = e; }
        int i1 = -1; float v1 = -3.0e38f;
        #pragma unroll
        for (int e = 0; e < NEXP; e++)
            if (e != i0 && logits[e] > v1) { v1 = logits[e]; i1 = e; }
        float e1 = __expf(v1 - v0);
        float inv = 1.0f / (1.0f + e1);
        int p0 = atomicAdd(&g_cnt[i0], 1);
        g_tok[i0 * MAXPER + p0] = t; g_wt[i0 * MAXPER + p0] = inv;
        int p1 = atomicAdd(&g_cnt[i1], 1);
        g_tok[i1 * MAXPER + p1] = t; g_wt[i1 * MAXPER + p1] = e1 * inv;
    }
}

// ===========================================================================
// Grouped GEMM, mma.sync m16n8k16 fp16.
//   A smem [m][AKH], 3 buffers, cp.async fills, ldmatrix.x4 fragments.
//   B smem [k][NST] (k-major), 2 buffers, coalesced LDG.128 + STS.64 fills,
//   ldmatrix.x4.trans fragments. ONE __syncthreads per K-chunk... (R8 exact)
// ===========================================================================
template <bool G1>
__global__ __launch_bounds__(256, 2)
void moe_gemm(const float* __restrict__ w,
              const float* __restrict__ bias,
              float* __restrict__ out) {
    constexpr int K  = G1 ? DMODEL : DFF;
    constexpr int NG = G1 ? DFF : DMODEL;
    constexpr int NC = K / BK;

    const int e = blockIdx.z;
    const int n = g_cnt[e];
    const int row0 = blockIdx.y * BM;
    if (row0 >= n) return;
    const int col0 = blockIdx.x * BN;

    extern __shared__ __half sm[];
    __half* As = sm;                    // [3][BM][AKH]
    __half* Bs = sm + 3 * ABUF_H;       // [2][BK][NST]

    const int tid = threadIdx.x, lane = tid & 31, wid = tid >> 5;
    const int wm = (wid & 1) * 64, wn = (wid >> 1) * 32;

    // ---- A fill: cp.async, 32B per thread per chunk ----
    const int ar = tid >> 1, ac = (tid & 1) * 16;
    const int rr = min(row0 + ar, n - 1);
    const __half* Ag;
    if (G1) Ag = g_xh + (size_t)g_tok[e * MAXPER + rr] * DMODEL + ac;
    else    Ag = g_h + ((size_t)e * MAXPER + rr) * DFF + ac;
    const uint32_t AsW = smem_u32(As) + (uint32_t)(ar * AKH + ac) * 2;

    // ---- B fill: thread -> 4 k-rows x 4 consecutive n (LDG.128) ----
    const int bq  = (tid & 31) * 4;          // n offset
    const int bk4 = (tid >> 5) * 4;          // base k-row
    const float* Bg = w + (size_t)e * DMODEL * DFF
                        + (size_t)bk4 * NG + col0 + bq;
    const uint32_t BsW = smem_u32(Bs) + (uint32_t)(bk4 * NST + bq) * 2;

    // ---- ldmatrix lane addresses (bytes) ----
    const uint32_t aFrag = smem_u32(As)
        + (uint32_t)(((wm + (lane & 15)) * AKH + (lane >> 4) * 8) * 2);
    const uint32_t bFrag = smem_u32(Bs)
        + (uint32_t)((((lane & 7) + ((lane >> 3) & 1) * 8) * NST
                      + wn + (lane >> 4) * 8) * 2);

    float4 bqv[4];

    #define LDG_B(c)                                                         \
        do { _Pragma("unroll")                                               \
             for (int i = 0; i < 4; i++)                                     \
                 bqv[i] = *(const float4*)(Bg + (size_t)((c) * BK + i) * NG);\
        } while (0)

    #define STS_B(buf)                                                       \
        do { _Pragma("unroll")                                               \
             for (int i = 0; i < 4; i++) {                                   \
                 __half2 lo = __floats2half2_rn(bqv[i].x, bqv[i].y);         \
                 __half2 hi = __floats2half2_rn(bqv[i].z, bqv[i].w);         \
                 uint2 v = make_uint2(*(uint32_t*)&lo, *(uint32_t*)&hi);     \
                 asm volatile("st.shared.v2.b32 [%0], {%1, %2};" ::          \
                     "r"(BsW + (buf) * (BBUF_H * 2) + i * (NST * 2)),        \
                     "r"(v.x), "r"(v.y));                                    \
             }                                                               \
        } while (0)

    #define CPA_A(c, slot)                                                   \
        do {                                                                  \
            const __half* ag = Ag + (c) * BK;                                 \
            const uint32_t aw = AsW + (slot) * (ABUF_H * 2);                  \
            CP_ASYNC16(aw, ag);                                               \
            CP_ASYNC16(aw + 16, ag + 8);                                      \
            CP_COMMIT();                                                      \
        } while (0)

    float acc[4][4][4];
    #pragma unroll
    for (int a = 0; a < 4; a++)
        #pragma unroll
        for (int b = 0; b < 4; b++)
            #pragma unroll
            for (int c = 0; c < 4; c++) acc[a][b][c] = 0.0f;

    // ---- prologue ----
    LDG_B(0);
    STS_B(0);
    CPA_A(0, 0);
    if (NC > 1) { CPA_A(1, 1); LDG_B(1); CP_WAIT1(); }
    else        { CP_WAIT0(); }
    __syncthreads();

    // ---- main loop: A rotates over 3 slots, B over 2 buffers ----
    int cur = 0;                         // A slot of chunk c
    for (int c = 0; c < NC; c++) {
        const uint32_t aB = aFrag + cur * (ABUF_H * 2);
        const uint32_t bB = bFrag + (c & 1) * (BBUF_H * 2);

        #pragma unroll
        for (int ks = 0; ks < 2; ks++) {
            uint32_t af[4][4];
            #pragma unroll
            for (int mt = 0; mt < 4; mt++)
                LDSM4(af[mt][0], af[mt][1], af[mt][2], af[mt][3],
                      aB + mt * (16 * AKH * 2) + ks * 32);
            uint32_t bf[4][2];
            LDSM4T(bf[0][0], bf[0][1], bf[1][0], bf[1][1],
                   bB + ks * (16 * NST * 2));
            LDSM4T(bf[2][0], bf[2][1], bf[3][0], bf[3][1],
                   bB + ks * (16 * NST * 2) + 32);      // +16 n = 32 bytes
            #pragma unroll
            for (int mt = 0; mt < 4; mt++)
                #pragma unroll
                for (int nt = 0; nt < 4; nt++)
                    asm volatile(
                        "mma.sync.aligned.m16n8k16.row.col.f32.f16.f16.f32 "
                        "{%0,%1,%2,%3},{%4,%5,%6,%7},{%8,%9},{%0,%1,%2,%3};"
                        : "+f"(acc[mt][nt][0]), "+f"(acc[mt][nt][1]),
                          "+f"(acc[mt][nt][2]), "+f"(acc[mt][nt][3])
                        : "r"(af[mt][0]), "r"(af[mt][1]),
                          "r"(af[mt][2]), "r"(af[mt][3]),
                          "r"(bf[nt][0]), "r"(bf[nt][1]));
        }

        if (c + 1 < NC) {
            STS_B((c + 1) & 1);                   // bqv holds chunk c+1
            if (c + 2 < NC) {
                int slot2 = cur >= 1 ? cur - 1 : cur + 2;   // (c+2)%3
                CPA_A(c + 2, slot2);
                LDG_B(c + 2);
                CP_WAIT1();                       // A(c+1) arrived
            } else {
                CP_WAIT0();
            }
            __syncthreads();
        }
        cur = (cur < 2) ? cur + 1 : 0;
    }

    // ---- epilogue ----
    #pragma unroll
    for (int mt = 0; mt < 4; mt++) {
        #pragma unroll
        for (int half = 0; half < 2; half++) {
            const int r = row0 + wm + mt * 16 + (lane >> 2) + half * 8;
            if (r >= n) continue;
            if (G1) {
                __half* Hp = g_h + ((size_t)e * MAXPER + r) * DFF + col0 + wn;
                const float* bp = bias + (size_t)e * DFF + col0 + wn;
                #pragma unroll
                for (int nt = 0; nt < 4; nt++) {
                    const int cc = nt * 8 + 2 * (lane & 3);
                    float vx = fmaxf(acc[mt][nt][half * 2 + 0] + bp[cc], 0.0f);
                    float vy = fmaxf(acc[mt][nt][half * 2 + 1] + bp[cc + 1], 0.0f);
                    *(__half2*)(Hp + cc) = __floats2half2_rn(vx, vy);
                }
            } else {
                const int   tok = g_tok[e * MAXPER + r];
                const float wt  = g_wt [e * MAXPER + r];
                float* op = out + (size_t)tok * DMODEL + col0 + wn;
                const float* bp = bias + (size_t)e * DMODEL + col0 + wn;
                #pragma unroll
                for (int nt = 0; nt < 4; nt++) {
                    const int cc = nt * 8 + 2 * (lane & 3);
                    atomicAdd(&op[cc],
                              wt * (acc[mt][nt][half * 2 + 0] + bp[cc]));
                    atomicAdd(&op[cc + 1],
                              wt * (acc[mt][nt][half * 2 + 1] + bp[cc + 1]));
                }
            }
        }
    }
    #undef LDG_B
    #undef STS_B
    #undef CPA_A
}

// ===========================================================================
extern "C" void kernel_launch(void* const* d_in, const int* in_sizes, int n_in,
                              void* d_out, int out_size) {
    const float* x  = (const float*)d_in[0];
    const float* wg = (const float*)d_in[1];
    const float* bg = (const float*)d_in[2];
    const float* w1 = (const float*)d_in[3];
    const float* b1 = (const float*)d_in[4];
    const float* w2 = (const float*)d_in[5];
    const float* b2 = (const float*)d_in[6];
    float* out = (float*)d_out;

    cudaFuncSetAttribute(moe_gemm<true>,
                         cudaFuncAttributeMaxDynamicSharedMemorySize, SMEM_BYTES);
    cudaFuncSetAttribute(moe_gemm<false>,
                         cudaFuncAttributeMaxDynamicSharedMemorySize, SMEM_BYTES);

    init_kernel<<<512, 256>>>(x, out, out_size);
    route_kernel<<<T_TOKENS, 256>>>(x, wg, bg);
    moe_gemm<true ><<<dim3(DFF / BN,    MAXPER / BM, NEXP), 256, SMEM_BYTES>>>
        (w1, b1, nullptr);
    moe_gemm<false><<<dim3(DMODEL / BN, MAXPER / BM, NEXP), 256, SMEM_BYTES>>>
        (w2, b2, out);
}